// round 2
// baseline (speedup 1.0000x reference)
#include <cuda_runtime.h>
#include <cstdint>
#include <cstddef>

#define B_ 8192
#define T_ 21
#define I_ 128
#define H1_ 256
#define H2_ 256
#define H3_ 128
#define M_ (B_*T_)   /* 172032 = 96*1792 exactly */

#define MT 96
#define SB 260            /* activation row stride (floats), ==4 mod 32 -> conflict-free frags */
#define WST 36            /* weight stage row stride (floats), ==4 mod 32 */
#define STG (3*32*WST)    /* floats per stage buffer (3 gates x 32 n x 32 k, padded) */

// -------- device scratch (allocation-free rule: __device__ globals) --------
__device__ float g_xt[(size_t)M_ * I_];   // 88 MB transposed, tf32-rounded x
__device__ float g_W1[3*H1_*I_];          // packed [i|g|o] weights, tf32-rounded
__device__ float g_W2[3*H2_*H1_];
__device__ float g_W3[3*H3_*H2_];
__device__ float g_b1[3*H1_];
__device__ float g_b2[3*H2_];
__device__ float g_b3[3*H3_];
__device__ float g_y[M_];                 // fc1 output (B,21)

// -------- helpers --------
__device__ __forceinline__ float tf32r(float f){
    uint32_t u; asm("cvt.rna.tf32.f32 %0, %1;" : "=r"(u) : "f"(f));
    return __uint_as_float(u);
}
__device__ __forceinline__ void cpa16(float* dst, const float* src){
    unsigned s = (unsigned)__cvta_generic_to_shared(dst);
    asm volatile("cp.async.ca.shared.global [%0], [%1], 16;" :: "r"(s), "l"(src));
}
__device__ __forceinline__ void cp_commit(){ asm volatile("cp.async.commit_group;"); }
template<int N> __device__ __forceinline__ void cp_wait(){ asm volatile("cp.async.wait_group %0;" :: "n"(N)); }

__device__ __forceinline__ void mma8(float* c, uint32_t a0,uint32_t a1,uint32_t a2,uint32_t a3,
                                     uint32_t b0, uint32_t b1){
    asm volatile(
      "mma.sync.aligned.m16n8k8.row.col.f32.tf32.tf32.f32 "
      "{%0,%1,%2,%3},{%4,%5,%6,%7},{%8,%9},{%0,%1,%2,%3};"
      : "+f"(c[0]),"+f"(c[1]),"+f"(c[2]),"+f"(c[3])
      : "r"(a0),"r"(a1),"r"(a2),"r"(a3),"r"(b0),"r"(b1));
}

__device__ __forceinline__ float sigmoidf_(float x){ return __fdividef(1.f, 1.f + __expf(-x)); }
__device__ __forceinline__ float tanhf2_(float x){ return 1.f - __fdividef(2.f, __expf(2.f*x) + 1.f); }

__device__ __forceinline__ int src_row(int n, int H){
    int blk = n / H, j = n - blk*H;
    return blk==0 ? j : (blk==1 ? 2*H + j : 3*H + j);   // gate order i,f,g,o: pick i,g,o
}

// -------- prep: pack + tf32-round weights, sum biases --------
__global__ void pack_kernel(const float* __restrict__ W1,const float* __restrict__ b1i,const float* __restrict__ b1h,
                            const float* __restrict__ W2,const float* __restrict__ b2i,const float* __restrict__ b2h,
                            const float* __restrict__ W3,const float* __restrict__ b3i,const float* __restrict__ b3h){
    int idx = blockIdx.x*blockDim.x + threadIdx.x;
    const int S1 = 3*H1_*I_, S2 = 3*H2_*H1_, S3 = 3*H3_*H2_;
    if (idx < S1){ int n = idx / I_,  k = idx % I_;  g_W1[idx] = tf32r(W1[(size_t)src_row(n,H1_)*I_  + k]); return; }
    idx -= S1;
    if (idx < S2){ int n = idx / H1_, k = idx % H1_; g_W2[idx] = tf32r(W2[(size_t)src_row(n,H2_)*H1_ + k]); return; }
    idx -= S2;
    if (idx < S3){ int n = idx / H2_, k = idx % H2_; g_W3[idx] = tf32r(W3[(size_t)src_row(n,H3_)*H2_ + k]); return; }
    idx -= S3;
    if (idx < 3*H1_){ int r = src_row(idx,H1_); g_b1[idx] = b1i[r] + b1h[r]; return; }
    idx -= 3*H1_;
    if (idx < 3*H2_){ int r = src_row(idx,H2_); g_b2[idx] = b2i[r] + b2h[r]; return; }
    idx -= 3*H2_;
    if (idx < 3*H3_){ int r = src_row(idx,H3_); g_b3[idx] = b3i[r] + b3h[r]; return; }
}

// -------- prep: x (B,I,T) -> xt (B*T, I), coalesced both sides, tf32-rounded --------
__global__ void transpose_kernel(const float* __restrict__ x){
    __shared__ float sx[I_*T_];
    int b = blockIdx.x, tid = threadIdx.x;   // 128 threads
    const float* xb = x + (size_t)b*I_*T_;
    #pragma unroll
    for (int j = tid; j < I_*T_; j += 128) sx[j] = xb[j];
    __syncthreads();
    #pragma unroll
    for (int t = 0; t < T_; ++t)
        g_xt[((size_t)(b*T_+t))*I_ + tid] = tf32r(sx[tid*T_ + t]);
}

// -------- fused LSTM-chain GEMM layer --------
template<int K, int H>
__device__ void layer_gemm(const float* __restrict__ Wp, const float* __restrict__ bp,
                           const float* actIn, float* actOut, float* wst, float* biasS){
    const int tid = threadIdx.x;            // 384 threads
    for (int i = tid; i < 3*H; i += 384) biasS[i] = bp[i];
    __syncthreads();
    const int warp = tid >> 5, lane = tid & 31;
    const int strip = warp >> 1, nh = warp & 1;   // 6 row strips x 2 n-halves = 12 warps
    const int g = lane >> 2, tq = lane & 3;
    const int mrow = strip*16;
    constexpr int NKC = K/32, NJC = H/32;

    for (int jc = 0; jc < NJC; ++jc){
        const int j0 = jc*32;
        float acc[3][2][4];
        #pragma unroll
        for (int a=0;a<3;++a)
            #pragma unroll
            for (int s=0;s<2;++s)
                #pragma unroll
                for (int p=0;p<4;++p) acc[a][s][p]=0.f;

        // prologue: stage kc = 0
        #pragma unroll
        for (int it=0; it<2; ++it){
            int c = tid + it*384;                          // 768 16B chunks
            int G = c >> 8, rem = c & 255, n = rem >> 3, k4 = rem & 7;
            cpa16(wst + G*(32*WST) + n*WST + k4*4,
                  Wp + (size_t)(G*H + j0 + n)*K + k4*4);
        }
        cp_commit();

        for (int kc = 0; kc < NKC; ++kc){
            if (kc+1 < NKC){
                float* dst = wst + ((kc+1)&1)*STG;
                #pragma unroll
                for (int it=0; it<2; ++it){
                    int c = tid + it*384;
                    int G = c >> 8, rem = c & 255, n = rem >> 3, k4 = rem & 7;
                    cpa16(dst + G*(32*WST) + n*WST + k4*4,
                          Wp + (size_t)(G*H + j0 + n)*K + (kc+1)*32 + k4*4);
                }
                cp_commit();
                cp_wait<1>();
            } else {
                cp_wait<0>();
            }
            __syncthreads();
            const float* ws = wst + (kc&1)*STG;
            #pragma unroll
            for (int ks=0; ks<4; ++ks){
                const int k = kc*32 + ks*8;
                const float* ar = actIn + (mrow+g)*SB + k + tq;
                uint32_t a0 = __float_as_uint(ar[0]);
                uint32_t a1 = __float_as_uint(ar[8*SB]);
                uint32_t a2 = __float_as_uint(ar[4]);
                uint32_t a3 = __float_as_uint(ar[8*SB+4]);
                #pragma unroll
                for (int G=0; G<3; ++G){
                    const float* wt = ws + G*(32*WST) + ks*8 + tq;
                    #pragma unroll
                    for (int s=0; s<2; ++s){
                        const int nl = nh*16 + s*8 + g;
                        uint32_t b0 = __float_as_uint(wt[nl*WST]);
                        uint32_t b1 = __float_as_uint(wt[nl*WST+4]);
                        mma8(acc[G][s], a0,a1,a2,a3, b0,b1);
                    }
                }
            }
            __syncthreads();
        }
        // combine: c = sig(i)*tanh(g); h = sig(o)*tanh(c)  (f-gate unused since c0=0)
        #pragma unroll
        for (int s=0; s<2; ++s){
            const int cbase = j0 + nh*16 + s*8 + 2*tq;
            #pragma unroll
            for (int p=0; p<4; ++p){
                const int q = p & 1, rr = p >> 1;
                const int c2 = cbase + q;
                float iv = acc[0][s][p] + biasS[c2];
                float gv = acc[1][s][p] + biasS[H + c2];
                float ov = acc[2][s][p] + biasS[2*H + c2];
                float cv = sigmoidf_(iv) * tanhf2_(gv);
                float h  = sigmoidf_(ov) * tanhf2_(cv);
                actOut[(mrow + g + 8*rr)*SB + c2] = tf32r(h);
            }
        }
    }
    __syncthreads();
}

__global__ void __launch_bounds__(384,1)
lstm_main(const float* __restrict__ fc1w, const float* __restrict__ fc1b){
    extern __shared__ float smem[];
    float* actA  = smem;                 // 96*260
    float* actB  = actA + MT*SB;         // 96*260
    float* wst   = actB + MT*SB;         // 2*STG
    float* biasS = wst + 2*STG;          // 768
    float* fcw   = biasS + 3*H1_;        // 128
    const int tid = threadIdx.x;
    const int m0 = blockIdx.x * MT;

    // load X tile (96 x 128) via cp.async
    #pragma unroll
    for (int it=0; it<8; ++it){
        int c = tid + it*384;            // 3072 chunks
        int r = c >> 5, k4 = c & 31;
        cpa16(actA + r*SB + k4*4, g_xt + (size_t)(m0+r)*I_ + k4*4);
    }
    if (tid < 128) fcw[tid] = fc1w[tid];
    cp_commit();
    cp_wait<0>();
    __syncthreads();

    layer_gemm<I_,  H1_>(g_W1, g_b1, actA, actB, wst, biasS);  // h1 in actB
    layer_gemm<H1_, H2_>(g_W2, g_b2, actB, actA, wst, biasS);  // h2 in actA
    layer_gemm<H2_, H3_>(g_W3, g_b3, actA, actB, wst, biasS);  // h3 in actB (96x128)

    if (tid < MT){
        const float* row = actB + tid*SB;
        float s = 0.f;
        #pragma unroll 8
        for (int i=0;i<I_;++i) s += row[i]*fcw[i];
        g_y[m0+tid] = s + fc1b[0];
    }
}

// -------- fc2: out[b,0,t] = sum_j y[b,j]*w[t,j] + bias[t] --------
__global__ void fc2_kernel(const float* __restrict__ w, const float* __restrict__ bias,
                           float* __restrict__ out){
    __shared__ float sw[T_*T_];
    __shared__ float sb[T_];
    int tid = threadIdx.x;               // 256
    for (int i = tid; i < T_*T_; i += 256) sw[i] = w[i];
    if (tid < T_) sb[tid] = bias[tid];
    __syncthreads();
    int gidx = blockIdx.x*256 + tid;     // exactly 172032 threads
    int b = gidx / T_, t = gidx - b*T_;
    const float* yb = g_y + (size_t)b*T_;
    float s = sb[t];
    #pragma unroll
    for (int j=0;j<T_;++j) s += yb[j]*sw[t*T_ + j];
    out[gidx] = s;
}

// -------- launch --------
extern "C" void kernel_launch(void* const* d_in, const int* in_sizes, int n_in,
                              void* d_out, int out_size){
    const float* x   = (const float*)d_in[0];
    const float* W1  = (const float*)d_in[1];
    const float* b1i = (const float*)d_in[2];
    const float* b1h = (const float*)d_in[3];
    const float* W2  = (const float*)d_in[4];
    const float* b2i = (const float*)d_in[5];
    const float* b2h = (const float*)d_in[6];
    const float* W3  = (const float*)d_in[7];
    const float* b3i = (const float*)d_in[8];
    const float* b3h = (const float*)d_in[9];
    const float* f1w = (const float*)d_in[10];
    const float* f1b = (const float*)d_in[11];
    const float* f2w = (const float*)d_in[12];
    const float* f2b = (const float*)d_in[13];
    float* out = (float*)d_out;

    const int SMEM_BYTES = (2*MT*SB + 2*STG + 3*H1_ + 128) * 4;  // 230912
    cudaFuncSetAttribute(lstm_main, cudaFuncAttributeMaxDynamicSharedMemorySize, SMEM_BYTES);

    pack_kernel<<<1544, 256>>>(W1,b1i,b1h,W2,b2i,b2h,W3,b3i,b3h);
    transpose_kernel<<<B_, 128>>>(x);
    lstm_main<<<M_/MT, 384, SMEM_BYTES>>>(f1w, f1b);
    fc2_kernel<<<M_/256, 256>>>(f2w, f2b, out);
}